// round 13
// baseline (speedup 1.0000x reference)
#include <cuda_runtime.h>
#include <cstdint>

// Q3 unpack -> float32 planes: final factor-grid cell (.cs + 16-word tile).
//
// Input:  4096x4096 int32; each word holds 10 x 3-bit fields at shifts
//         27,24,...,0.  Output: [10*4096, 4096] float32; plane k =
//         (float)((w >> (27-3k)) & 7), input's linear layout at offset
//         k * n_words.
//
// Thread i: 16 consecutive words (4 x LDG.128 .cs, 4-deep MLP) -> 2 x
// st.global.cs.v8.b32 per plane (2KB contiguous per warp per plane).
// Completes the {store-policy x tile-width} grid: R5 (.cs,8w)=115.0us,
// R6 (default,16w)=119.7us; this isolates the width factor under the
// winning .cs policy. Traffic 67MB in + 671MB out, HBM-bound at the
// ~5.95 TB/s write-dominated ceiling.

__device__ __forceinline__ void stg_cs_v8(float* p, const unsigned int* v)
{
    asm volatile(
        "st.global.cs.v8.b32 [%0], {%1, %2, %3, %4, %5, %6, %7, %8};"
        :: "l"(p),
           "r"(v[0]), "r"(v[1]), "r"(v[2]), "r"(v[3]),
           "r"(v[4]), "r"(v[5]), "r"(v[6]), "r"(v[7])
        : "memory");
}

__global__ void __launch_bounds__(256)
q3_unpack_f32_x16cs_kernel(const uint4* __restrict__ in,
                           float* __restrict__ out,
                           int ntile)  // number of 16-word tiles (= words/16)
{
    int i = blockIdx.x * blockDim.x + threadIdx.x;
    if (i >= ntile) return;

    uint4 w[4];
#pragma unroll
    for (int j = 0; j < 4; ++j)
        w[j] = __ldcs(in + 4 * (size_t)i + j);

    const unsigned int* ws = (const unsigned int*)w;  // 16 packed words

    const size_t plane = (size_t)ntile * 16;  // plane stride in floats
    float* o = out + (size_t)i * 16;

#pragma unroll
    for (int k = 0; k < 10; ++k) {
        const int s = 27 - 3 * k;
        unsigned int v[16];
#pragma unroll
        for (int j = 0; j < 16; ++j)
            v[j] = __float_as_uint((float)((ws[j] >> s) & 7u));
        float* p = o + (size_t)k * plane;
        stg_cs_v8(p, v);
        stg_cs_v8(p + 8, v + 8);
    }
}

extern "C" void kernel_launch(void* const* d_in, const int* in_sizes, int n_in,
                              void* d_out, int out_size)
{
    (void)n_in; (void)out_size;
    const int n_words = in_sizes[0];      // 4096*4096 = 16,777,216
    const int ntile   = n_words >> 4;     // 1,048,576

    const uint4* in = (const uint4*)d_in[0];
    float* out = (float*)d_out;

    const int threads = 256;
    const int blocks  = (ntile + threads - 1) / threads;  // 4096
    q3_unpack_f32_x16cs_kernel<<<blocks, threads>>>(in, out, ntile);
}

// round 15
// speedup vs baseline: 1.0485x; 1.0485x over previous
#include <cuda_runtime.h>
#include <cstdint>

// Q3 unpack -> float32 planes. FINAL (R5, measured best; reproduced twice at
// 115.0/114.6us ncu, 118.2/118.3us bench). Resubmitted unchanged after a
// broker/container infra failure on the previous attempt.
//
// Input:  4096x4096 int32; each word holds 10 x 3-bit fields at shifts
//         27,24,...,0.  Output: [10*4096, 4096] float32; plane k =
//         (float)((w >> (27-3k)) & 7), same linear layout as the input at
//         element offset k * n_words.
//
// Thread i handles 8 consecutive words (2 x LDG.128 .cs) and emits one
// 32-byte st.global.cs.v8.b32 per plane (1KB contiguous per warp per plane).
// Traffic: 67MB in + 671MB out, zero reuse.
//
// Optimization space fully measured: store width {16B,32B}, tile {4,8,16
// words}, policy {.cs, default}, stream shape {10-way interleaved, per-warp
// contiguous via smem staging, warp-per-plane}. All land at 70-74% DRAM;
// this variant is fastest (5.96 TB/s = the write-dominated HBM ceiling) and
// simplest (32 regs, no smem, no syncs, 88% occupancy, 14% issue).

__device__ __forceinline__ void stg_cs_v8(float* p,
                                          float v0, float v1, float v2, float v3,
                                          float v4, float v5, float v6, float v7)
{
    asm volatile(
        "st.global.cs.v8.b32 [%0], {%1, %2, %3, %4, %5, %6, %7, %8};"
        :: "l"(p),
           "r"(__float_as_uint(v0)), "r"(__float_as_uint(v1)),
           "r"(__float_as_uint(v2)), "r"(__float_as_uint(v3)),
           "r"(__float_as_uint(v4)), "r"(__float_as_uint(v5)),
           "r"(__float_as_uint(v6)), "r"(__float_as_uint(v7))
        : "memory");
}

__global__ void __launch_bounds__(256)
q3_unpack_f32_v8_kernel(const uint4* __restrict__ in,
                        float* __restrict__ out,
                        int nvec8)  // number of 8-word groups (= words/8)
{
    int i = blockIdx.x * blockDim.x + threadIdx.x;
    if (i >= nvec8) return;

    const uint4 a = __ldcs(in + 2 * (size_t)i);
    const uint4 b = __ldcs(in + 2 * (size_t)i + 1);

    const size_t plane = (size_t)nvec8 * 8;   // plane stride in floats
    float* o = out + (size_t)i * 8;

#pragma unroll
    for (int k = 0; k < 10; ++k) {
        const int s = 27 - 3 * k;
        stg_cs_v8(o + (size_t)k * plane,
                  (float)((a.x >> s) & 7u), (float)((a.y >> s) & 7u),
                  (float)((a.z >> s) & 7u), (float)((a.w >> s) & 7u),
                  (float)((b.x >> s) & 7u), (float)((b.y >> s) & 7u),
                  (float)((b.z >> s) & 7u), (float)((b.w >> s) & 7u));
    }
}

extern "C" void kernel_launch(void* const* d_in, const int* in_sizes, int n_in,
                              void* d_out, int out_size)
{
    (void)n_in; (void)out_size;
    const int n_words = in_sizes[0];      // 4096*4096 = 16,777,216
    const int nvec8   = n_words >> 3;     // 2,097,152

    const uint4* in = (const uint4*)d_in[0];
    float* out = (float*)d_out;

    const int threads = 256;
    const int blocks  = (nvec8 + threads - 1) / threads;  // 8192
    q3_unpack_f32_v8_kernel<<<blocks, threads>>>(in, out, nvec8);
}